// round 7
// baseline (speedup 1.0000x reference)
#include <cuda_runtime.h>
#include <cuda_bf16.h>
#include <cstdint>

// Problem constants (fixed by setup_inputs)
#define NB 16      // batch
#define LL 512     // sequence length
#define DD 256     // encoder dim = filter size
#define TT 4096    // WVF_max_length
#define TP 16      // L-positions per conv block

// Intermediates (no cudaMalloc allowed) — referenced directly from device code.
__device__ float g_h1[NB * LL * DD];
__device__ int   g_dur[NB * LL];
__device__ int   g_lmap[NB * TT];
__device__ float g_wT1[3 * DD * 256];   // conv1_w transposed: [kk][f][d]
__device__ float g_wT2[3 * DD * 256];   // conv2_w transposed: [kk][f][d]

// ---- packed fp32x2 helpers (sm_100a; ptxas never auto-emits FFMA2) ----
__device__ __forceinline__ void fma2(unsigned long long& acc,
                                     unsigned long long a,
                                     unsigned long long b)
{
    asm("fma.rn.f32x2 %0, %1, %2, %0;" : "+l"(acc) : "l"(a), "l"(b));
}
__device__ __forceinline__ float2 unpack2(unsigned long long v)
{
    float2 r;
    asm("mov.b64 {%0, %1}, %2;" : "=f"(r.x), "=f"(r.y) : "l"(v));
    return r;
}

// ---------------------------------------------------------------------------
// Weight transpose: w[kk][d][f] -> wT[kk][f][d], both conv layers in one grid.
// grid (8, 8, 6): z = tensor*3 + kk; block (32, 8).
// ---------------------------------------------------------------------------
__global__ void __launch_bounds__(256) transpose_w_kernel(
    const float* __restrict__ w1, const float* __restrict__ w2)
{
    __shared__ float tile[32][33];
    const int z = blockIdx.z;
    const float* src = (z < 3) ? w1 : w2;
    float* dst = (z < 3) ? g_wT1 : g_wT2;
    const int kk = (z < 3) ? z : z - 3;
    src += kk * (DD * 256);
    dst += kk * (DD * 256);
    const int d0 = blockIdx.y * 32, f0 = blockIdx.x * 32;
    const int tx = threadIdx.x, ty = threadIdx.y;
    #pragma unroll
    for (int j = 0; j < 4; j++)
        tile[ty + 8 * j][tx] = src[(d0 + ty + 8 * j) * 256 + f0 + tx];
    __syncthreads();
    #pragma unroll
    for (int j = 0; j < 4; j++)
        dst[(f0 + ty + 8 * j) * 256 + d0 + tx] = tile[tx][ty + 8 * j];
}

// ---------------------------------------------------------------------------
// Fused conv1d(K=3, same pad) + bias + LayerNorm(F) + ReLU
// STAGE 0: src = x, wT = g_wT1, writes h to g_h1.
// STAGE 1: src = g_h1, wT = g_wT2, fuses the final linear + duration:
//          dur[n,l] = int(relu(h.lin_w + lin_b) + 0.5) — h2 never hits gmem.
// One block = 16 consecutive L positions, 256 threads (one per output chan f).
// Per-thread weights loaded as contiguous LDG.128 along d (transposed layout);
// register pairs are directly valid b64 operands for fma.rn.f32x2.
// ---------------------------------------------------------------------------
template<int STAGE>
__global__ void __launch_bounds__(256) conv_ln_relu_kernel(
    const float* __restrict__ x,
    const float* __restrict__ bias,
    const float* __restrict__ gamma,
    const float* __restrict__ beta,
    const float* __restrict__ lin_w,
    const float* __restrict__ lin_b)
{
    __shared__ float xs[TP + 2][DD];   // 18 KB input rows
    __shared__ float hs[TP][DD];       // 16 KB tile for LN stats / dot products
    __shared__ float mu_s[TP];
    __shared__ float rs_s[TP];

    const float* __restrict__ src = (STAGE == 0) ? x : (const float*)g_h1;
    const float* __restrict__ wT  = (STAGE == 0) ? (const float*)g_wT1 : (const float*)g_wT2;

    const int blk = blockIdx.x;
    const int n   = blk / (LL / TP);
    const int l0  = (blk % (LL / TP)) * TP;
    const int f   = threadIdx.x;

    // Load input rows (zero padding at sequence edges)
    #pragma unroll
    for (int r = 0; r < TP + 2; r++) {
        int l = l0 - 1 + r;
        xs[r][f] = (l >= 0 && l < LL) ? src[(n * LL + l) * DD + f] : 0.f;
    }
    __syncthreads();

    // acc2[p] = (sum over even d, sum over odd d) packed fp32x2
    unsigned long long acc2[TP];
    #pragma unroll
    for (int p = 0; p < TP; p++) acc2[p] = 0ull;

    const float* wf = wT + f * 256;   // this thread's weight rows, d-contiguous

    // Mainloop: d in steps of 8.
    // Per step: 6 LDG.128 (weights), 36 LDS.128 (broadcast), 192 FFMA2.
    #pragma unroll 1
    for (int d = 0; d < DD; d += 8) {
        unsigned long long wk[3][4];
        #pragma unroll
        for (int kk = 0; kk < 3; kk++) {
            const ulonglong2 t0 = *(const ulonglong2*)(wf + kk * (DD * 256) + d);
            const ulonglong2 t1 = *(const ulonglong2*)(wf + kk * (DD * 256) + d + 4);
            wk[kk][0] = t0.x; wk[kk][1] = t0.y;
            wk[kk][2] = t1.x; wk[kk][3] = t1.y;
        }
        #pragma unroll
        for (int r = 0; r < TP + 2; r++) {
            const ulonglong2 xv0 = *(const ulonglong2*)&xs[r][d];
            const ulonglong2 xv1 = *(const ulonglong2*)&xs[r][d + 4];
            #pragma unroll
            for (int kk = 0; kk < 3; kk++) {
                const int p = r - kk;      // output position using row r at tap kk
                if (p >= 0 && p < TP) {    // compile-time after unroll
                    fma2(acc2[p], xv0.x, wk[kk][0]);
                    fma2(acc2[p], xv0.y, wk[kk][1]);
                    fma2(acc2[p], xv1.x, wk[kk][2]);
                    fma2(acc2[p], xv1.y, wk[kk][3]);
                }
            }
        }
    }

    // Horizontal combine + bias; stage into hs for LayerNorm stats
    float acc[TP];
    {
        const float bf = bias[f];
        #pragma unroll
        for (int p = 0; p < TP; p++) {
            float2 v = unpack2(acc2[p]);
            acc[p] = v.x + v.y + bf;
            hs[p][f] = acc[p];
        }
    }
    __syncthreads();

    // LayerNorm over f (256) per position p: warp-parallel reductions
    {
        const int wid = f >> 5, lane = f & 31;
        #pragma unroll
        for (int rr = 0; rr < 2; rr++) {
            int r = wid * 2 + rr;
            float s = 0.f, s2 = 0.f;
            #pragma unroll
            for (int c0 = 0; c0 < 256; c0 += 32) {
                float v = hs[r][c0 + lane];
                s += v; s2 += v * v;
            }
            #pragma unroll
            for (int o = 16; o; o >>= 1) {
                s  += __shfl_xor_sync(0xFFFFFFFFu, s,  o);
                s2 += __shfl_xor_sync(0xFFFFFFFFu, s2, o);
            }
            if (lane == 0) {
                float mu = s * (1.f / 256.f);
                float var = s2 * (1.f / 256.f) - mu * mu;
                mu_s[r] = mu;
                rs_s[r] = rsqrtf(var + 1e-5f);
            }
        }
    }
    __syncthreads();

    if (STAGE == 0) {
        const float gg = gamma[f], bb = beta[f];
        #pragma unroll
        for (int p = 0; p < TP; p++) {
            float v = (acc[p] - mu_s[p]) * rs_s[p] * gg + bb;
            g_h1[(n * LL + l0 + p) * 256 + f] = fmaxf(v, 0.f);
        }
    } else {
        // Fused linear head: prod[p][f] = relu(LN(h)) * lin_w[f], reduce over f.
        const float gg = gamma[f], bb = beta[f];
        const float lw = lin_w[f];
        #pragma unroll
        for (int p = 0; p < TP; p++) {
            float v = fmaxf((acc[p] - mu_s[p]) * rs_s[p] * gg + bb, 0.f);
            hs[p][f] = v * lw;   // hs free after LN stats sync
        }
        __syncthreads();
        {
            const int wid = f >> 5, lane = f & 31;
            const float lb = lin_b[0];
            #pragma unroll
            for (int rr = 0; rr < 2; rr++) {
                int r = wid * 2 + rr;
                float s = 0.f;
                #pragma unroll
                for (int c0 = 0; c0 < 256; c0 += 32)
                    s += hs[r][c0 + lane];
                #pragma unroll
                for (int o = 16; o; o >>= 1)
                    s += __shfl_xor_sync(0xFFFFFFFFu, s, o);
                if (lane == 0) {
                    float dpo = fmaxf(s + lb, 0.f);
                    g_dur[n * LL + l0 + r] = (int)(dpo + 0.5f);
                }
            }
        }
    }
}

// ---------------------------------------------------------------------------
// Inclusive scan of durations per row + t -> l binary-search map.
// One block per n, 512 threads. Tiny (reads 2 KB/row).
// ---------------------------------------------------------------------------
__global__ void __launch_bounds__(512) scan_map_kernel()
{
    const int n = blockIdx.x;
    const int l = threadIdx.x;

    __shared__ int sc[LL];
    sc[l] = g_dur[n * LL + l];
    __syncthreads();
    for (int off = 1; off < LL; off <<= 1) {
        int v = (l >= off) ? sc[l - off] : 0;
        __syncthreads();
        sc[l] += v;
        __syncthreads();
    }

    const int total = sc[LL - 1];
    for (int t = l; t < TT; t += LL) {
        int res = -1;
        if (t < total) {
            int lo = 0, hi = LL - 1;
            while (lo < hi) {
                int mid = (lo + hi) >> 1;
                if (sc[mid] > t) hi = mid; else lo = mid + 1;
            }
            res = lo;
        }
        g_lmap[n * TT + t] = res;
    }
}

// ---------------------------------------------------------------------------
// out[n, t, :] = x[n, lmap[n,t], :]  (or zeros). float4 streaming copy.
// ---------------------------------------------------------------------------
__global__ void __launch_bounds__(256) expand_copy_kernel(
    const float* __restrict__ x,
    float* __restrict__ out)
{
    const int idx = blockIdx.x * blockDim.x + threadIdx.x;  // over NB*TT*64 float4
    const int c = idx & 63;
    const int t = (idx >> 6) & (TT - 1);
    const int n = idx >> 18;
    const int l = g_lmap[n * TT + t];
    float4 v = make_float4(0.f, 0.f, 0.f, 0.f);
    if (l >= 0) v = ((const float4*)x)[(n * LL + l) * (DD / 4) + c];
    ((float4*)out)[idx] = v;
}

// ---------------------------------------------------------------------------
// Optional second output: WVF_pos = 1..TT (if the harness concatenated it)
// ---------------------------------------------------------------------------
__global__ void tail_kernel(float* __restrict__ out, int tail)
{
    int i = blockIdx.x * blockDim.x + threadIdx.x;
    if (i < tail) out[NB * TT * DD + i] = (float)((i % TT) + 1);
}

extern "C" void kernel_launch(void* const* d_in, const int* in_sizes, int n_in,
                              void* d_out, int out_size)
{
    const float* x       = (const float*)d_in[0];
    const float* conv1_w = (const float*)d_in[1];
    const float* conv1_b = (const float*)d_in[2];
    const float* ln1_g   = (const float*)d_in[3];
    const float* ln1_b   = (const float*)d_in[4];
    const float* conv2_w = (const float*)d_in[5];
    const float* conv2_b = (const float*)d_in[6];
    const float* ln2_g   = (const float*)d_in[7];
    const float* ln2_b   = (const float*)d_in[8];
    const float* lin_w   = (const float*)d_in[9];
    const float* lin_b   = (const float*)d_in[10];

    float* out = (float*)d_out;

    // Pure kernel launches only — fully graph-capturable.
    {
        dim3 tg(8, 8, 6), tb(32, 8);
        transpose_w_kernel<<<tg, tb>>>(conv1_w, conv2_w);
    }
    const int conv_grid = NB * (LL / TP);   // 512
    conv_ln_relu_kernel<0><<<conv_grid, 256>>>(x, conv1_b, ln1_g, ln1_b, lin_w, lin_b);
    conv_ln_relu_kernel<1><<<conv_grid, 256>>>(x, conv2_b, ln2_g, ln2_b, lin_w, lin_b);
    scan_map_kernel<<<NB, LL>>>();

    const int n_f4 = NB * TT * (DD / 4);    // 4,194,304
    expand_copy_kernel<<<n_f4 / 256, 256>>>(x, out);

    const int main_elems = NB * TT * DD;
    int tail = out_size - main_elems;
    if (tail > 0) {
        tail_kernel<<<(tail + 255) / 256, 256>>>(out, tail);
    }
}

// round 8
// speedup vs baseline: 2.0151x; 2.0151x over previous
#include <cuda_runtime.h>
#include <cuda_bf16.h>
#include <cstdint>

// Problem constants (fixed by setup_inputs)
#define NB 16      // batch
#define LL 512     // sequence length
#define DD 256     // encoder dim = filter size
#define TT 4096    // WVF_max_length
#define TP 16      // L-positions per conv block

// Intermediates (no cudaMalloc allowed) — referenced directly from device code.
__device__ float g_h1[NB * LL * DD];
__device__ int   g_dur[NB * LL];
__device__ int   g_lmap[NB * TT];
// Pair-packed weights: wp[kk][d2][f] = (w[kk][2*d2][f], w[kk][2*d2+1][f]) as b64.
// f stays the fastest axis -> LDG.64 with 8B lane stride, fully coalesced.
__device__ unsigned long long g_wp1[3 * (DD / 2) * 256];
__device__ unsigned long long g_wp2[3 * (DD / 2) * 256];

// ---- packed fp32x2 helpers (sm_100a; ptxas never auto-emits FFMA2) ----
__device__ __forceinline__ void fma2(unsigned long long& acc,
                                     unsigned long long a,
                                     unsigned long long b)
{
    asm("fma.rn.f32x2 %0, %1, %2, %0;" : "+l"(acc) : "l"(a), "l"(b));
}
__device__ __forceinline__ unsigned long long pack2(float a, float b)
{
    unsigned long long r;
    asm("mov.b64 %0, {%1, %2};" : "=l"(r) : "f"(a), "f"(b));
    return r;
}
__device__ __forceinline__ float2 unpack2(unsigned long long v)
{
    float2 r;
    asm("mov.b64 {%0, %1}, %2;" : "=f"(r.x), "=f"(r.y) : "l"(v));
    return r;
}

// ---------------------------------------------------------------------------
// Weight pair-packing: w[kk][d][f] -> wp[kk][d/2][f] (b64 of two d-adjacent
// values). Reads and writes both coalesced along f.
// grid: 2 * 3 * 128 blocks of 256 threads.
// ---------------------------------------------------------------------------
__global__ void __launch_bounds__(256) pack_w_kernel(
    const float* __restrict__ w1, const float* __restrict__ w2)
{
    const int b = blockIdx.x;           // 0..767: tensor*384 + kk*128 + d2
    const int tensor = b / 384;
    const int kk = (b % 384) / 128;
    const int d2 = b % 128;
    const int f  = threadIdx.x;
    const float* src = (tensor == 0) ? w1 : w2;
    unsigned long long* dst = (tensor == 0) ? g_wp1 : g_wp2;
    const float a = src[kk * (DD * 256) + (2 * d2)     * 256 + f];
    const float c = src[kk * (DD * 256) + (2 * d2 + 1) * 256 + f];
    dst[kk * ((DD / 2) * 256) + d2 * 256 + f] = pack2(a, c);
}

// ---------------------------------------------------------------------------
// Fused conv1d(K=3, same pad) + bias + LayerNorm(F) + ReLU
// STAGE 0: src = x, wp = g_wp1, writes h to g_h1.
// STAGE 1: src = g_h1, wp = g_wp2, fuses the final linear + duration:
//          dur[n,l] = int(relu(h.lin_w + lin_b) + 0.5) — h2 never hits gmem.
// One block = 16 consecutive L positions, 256 threads (one per output chan f).
// ---------------------------------------------------------------------------
template<int STAGE>
__global__ void __launch_bounds__(256) conv_ln_relu_kernel(
    const float* __restrict__ x,
    const float* __restrict__ bias,
    const float* __restrict__ gamma,
    const float* __restrict__ beta,
    const float* __restrict__ lin_w,
    const float* __restrict__ lin_b)
{
    __shared__ float xs[TP + 2][DD];   // 18 KB input rows
    __shared__ float hs[TP][DD];       // 16 KB tile for LN stats / dot products
    __shared__ float mu_s[TP];
    __shared__ float rs_s[TP];

    const float* __restrict__ src = (STAGE == 0) ? x : (const float*)g_h1;
    const unsigned long long* __restrict__ wp =
        (STAGE == 0) ? (const unsigned long long*)g_wp1
                     : (const unsigned long long*)g_wp2;

    const int blk = blockIdx.x;
    const int n   = blk / (LL / TP);
    const int l0  = (blk % (LL / TP)) * TP;
    const int f   = threadIdx.x;

    // Load input rows (zero padding at sequence edges)
    #pragma unroll
    for (int r = 0; r < TP + 2; r++) {
        int l = l0 - 1 + r;
        xs[r][f] = (l >= 0 && l < LL) ? src[(n * LL + l) * DD + f] : 0.f;
    }
    __syncthreads();

    // acc2[p] = (sum over even d, sum over odd d) packed fp32x2
    unsigned long long acc2[TP];
    #pragma unroll
    for (int p = 0; p < TP; p++) acc2[p] = 0ull;

    const unsigned long long* wf = wp + f;   // this thread's column

    // Mainloop: d in steps of 4 (= 2 packed pairs).
    // Per step: 6 coalesced LDG.64 (weights), 18 LDS.128 (broadcast), 96 FFMA2.
    #pragma unroll 2
    for (int d2 = 0; d2 < DD / 2; d2 += 2) {
        unsigned long long wk01[3], wk23[3];
        #pragma unroll
        for (int kk = 0; kk < 3; kk++) {
            const unsigned long long* wkk = wf + kk * ((DD / 2) * 256);
            wk01[kk] = wkk[d2 * 256];
            wk23[kk] = wkk[(d2 + 1) * 256];
        }
        #pragma unroll
        for (int r = 0; r < TP + 2; r++) {
            // one LDS.128 -> two aligned b64 operands (broadcast across lanes)
            const ulonglong2 xv = *(const ulonglong2*)&xs[r][d2 * 2];
            #pragma unroll
            for (int kk = 0; kk < 3; kk++) {
                const int p = r - kk;      // output position using row r at tap kk
                if (p >= 0 && p < TP) {    // compile-time after unroll
                    fma2(acc2[p], xv.x, wk01[kk]);
                    fma2(acc2[p], xv.y, wk23[kk]);
                }
            }
        }
    }

    // Horizontal combine + bias; stage into hs for LayerNorm stats
    float acc[TP];
    {
        const float bf = bias[f];
        #pragma unroll
        for (int p = 0; p < TP; p++) {
            float2 v = unpack2(acc2[p]);
            acc[p] = v.x + v.y + bf;
            hs[p][f] = acc[p];
        }
    }
    __syncthreads();

    // LayerNorm over f (256) per position p: warp-parallel reductions
    {
        const int wid = f >> 5, lane = f & 31;
        #pragma unroll
        for (int rr = 0; rr < 2; rr++) {
            int r = wid * 2 + rr;
            float s = 0.f, s2 = 0.f;
            #pragma unroll
            for (int c0 = 0; c0 < 256; c0 += 32) {
                float v = hs[r][c0 + lane];
                s += v; s2 += v * v;
            }
            #pragma unroll
            for (int o = 16; o; o >>= 1) {
                s  += __shfl_xor_sync(0xFFFFFFFFu, s,  o);
                s2 += __shfl_xor_sync(0xFFFFFFFFu, s2, o);
            }
            if (lane == 0) {
                float mu = s * (1.f / 256.f);
                float var = s2 * (1.f / 256.f) - mu * mu;
                mu_s[r] = mu;
                rs_s[r] = rsqrtf(var + 1e-5f);
            }
        }
    }
    __syncthreads();

    if (STAGE == 0) {
        const float gg = gamma[f], bb = beta[f];
        #pragma unroll
        for (int p = 0; p < TP; p++) {
            float v = (acc[p] - mu_s[p]) * rs_s[p] * gg + bb;
            g_h1[(n * LL + l0 + p) * 256 + f] = fmaxf(v, 0.f);
        }
    } else {
        // Fused linear head: prod[p][f] = relu(LN(h)) * lin_w[f], reduce over f.
        const float gg = gamma[f], bb = beta[f];
        const float lw = lin_w[f];
        #pragma unroll
        for (int p = 0; p < TP; p++) {
            float v = fmaxf((acc[p] - mu_s[p]) * rs_s[p] * gg + bb, 0.f);
            hs[p][f] = v * lw;   // hs free after LN stats sync
        }
        __syncthreads();
        {
            const int wid = f >> 5, lane = f & 31;
            const float lb = lin_b[0];
            #pragma unroll
            for (int rr = 0; rr < 2; rr++) {
                int r = wid * 2 + rr;
                float s = 0.f;
                #pragma unroll
                for (int c0 = 0; c0 < 256; c0 += 32)
                    s += hs[r][c0 + lane];
                #pragma unroll
                for (int o = 16; o; o >>= 1)
                    s += __shfl_xor_sync(0xFFFFFFFFu, s, o);
                if (lane == 0) {
                    float dpo = fmaxf(s + lb, 0.f);
                    g_dur[n * LL + l0 + r] = (int)(dpo + 0.5f);
                }
            }
        }
    }
}

// ---------------------------------------------------------------------------
// Inclusive scan of durations per row + t -> l binary-search map.
// One block per n, 512 threads. Tiny (reads 2 KB/row).
// ---------------------------------------------------------------------------
__global__ void __launch_bounds__(512) scan_map_kernel()
{
    const int n = blockIdx.x;
    const int l = threadIdx.x;

    __shared__ int sc[LL];
    sc[l] = g_dur[n * LL + l];
    __syncthreads();
    for (int off = 1; off < LL; off <<= 1) {
        int v = (l >= off) ? sc[l - off] : 0;
        __syncthreads();
        sc[l] += v;
        __syncthreads();
    }

    const int total = sc[LL - 1];
    for (int t = l; t < TT; t += LL) {
        int res = -1;
        if (t < total) {
            int lo = 0, hi = LL - 1;
            while (lo < hi) {
                int mid = (lo + hi) >> 1;
                if (sc[mid] > t) hi = mid; else lo = mid + 1;
            }
            res = lo;
        }
        g_lmap[n * TT + t] = res;
    }
}

// ---------------------------------------------------------------------------
// out[n, t, :] = x[n, lmap[n,t], :]  (or zeros). float4 streaming copy.
// ---------------------------------------------------------------------------
__global__ void __launch_bounds__(256) expand_copy_kernel(
    const float* __restrict__ x,
    float* __restrict__ out)
{
    const int idx = blockIdx.x * blockDim.x + threadIdx.x;  // over NB*TT*64 float4
    const int c = idx & 63;
    const int t = (idx >> 6) & (TT - 1);
    const int n = idx >> 18;
    const int l = g_lmap[n * TT + t];
    float4 v = make_float4(0.f, 0.f, 0.f, 0.f);
    if (l >= 0) v = ((const float4*)x)[(n * LL + l) * (DD / 4) + c];
    ((float4*)out)[idx] = v;
}

// ---------------------------------------------------------------------------
// Optional second output: WVF_pos = 1..TT (if the harness concatenated it)
// ---------------------------------------------------------------------------
__global__ void tail_kernel(float* __restrict__ out, int tail)
{
    int i = blockIdx.x * blockDim.x + threadIdx.x;
    if (i < tail) out[NB * TT * DD + i] = (float)((i % TT) + 1);
}

extern "C" void kernel_launch(void* const* d_in, const int* in_sizes, int n_in,
                              void* d_out, int out_size)
{
    const float* x       = (const float*)d_in[0];
    const float* conv1_w = (const float*)d_in[1];
    const float* conv1_b = (const float*)d_in[2];
    const float* ln1_g   = (const float*)d_in[3];
    const float* ln1_b   = (const float*)d_in[4];
    const float* conv2_w = (const float*)d_in[5];
    const float* conv2_b = (const float*)d_in[6];
    const float* ln2_g   = (const float*)d_in[7];
    const float* ln2_b   = (const float*)d_in[8];
    const float* lin_w   = (const float*)d_in[9];
    const float* lin_b   = (const float*)d_in[10];

    float* out = (float*)d_out;

    // Pure kernel launches only — fully graph-capturable.
    pack_w_kernel<<<2 * 3 * (DD / 2), 256>>>(conv1_w, conv2_w);

    const int conv_grid = NB * (LL / TP);   // 512
    conv_ln_relu_kernel<0><<<conv_grid, 256>>>(x, conv1_b, ln1_g, ln1_b, lin_w, lin_b);
    conv_ln_relu_kernel<1><<<conv_grid, 256>>>(x, conv2_b, ln2_g, ln2_b, lin_w, lin_b);
    scan_map_kernel<<<NB, LL>>>();

    const int n_f4 = NB * TT * (DD / 4);    // 4,194,304
    expand_copy_kernel<<<n_f4 / 256, 256>>>(x, out);

    const int main_elems = NB * TT * DD;
    int tail = out_size - main_elems;
    if (tail > 0) {
        tail_kernel<<<(tail + 255) / 256, 256>>>(out, tail);
    }
}

// round 9
// speedup vs baseline: 2.1053x; 1.0448x over previous
#include <cuda_runtime.h>
#include <cuda_bf16.h>
#include <cstdint>

// Problem constants (fixed by setup_inputs)
#define NB 16      // batch
#define LL 512     // sequence length
#define DD 256     // encoder dim = filter size
#define TT 4096    // WVF_max_length
#define TP 32      // L-positions per conv block

// Intermediates (no cudaMalloc allowed) — referenced directly from device code.
__device__ float g_h1[NB * LL * DD];
__device__ int   g_dur[NB * LL];
__device__ int   g_lmap[NB * TT];
// Pair-packed weights: wp[kk][d2][f] = (w[kk][2*d2][f], w[kk][2*d2+1][f]) as b64.
// f stays the fastest axis -> LDG.64 with 8B lane stride, fully coalesced.
__device__ unsigned long long g_wp1[3 * (DD / 2) * 256];
__device__ unsigned long long g_wp2[3 * (DD / 2) * 256];

// ---- packed fp32x2 helpers (sm_100a; ptxas never auto-emits FFMA2) ----
__device__ __forceinline__ void fma2(unsigned long long& acc,
                                     unsigned long long a,
                                     unsigned long long b)
{
    asm("fma.rn.f32x2 %0, %1, %2, %0;" : "+l"(acc) : "l"(a), "l"(b));
}
__device__ __forceinline__ unsigned long long pack2(float a, float b)
{
    unsigned long long r;
    asm("mov.b64 %0, {%1, %2};" : "=l"(r) : "f"(a), "f"(b));
    return r;
}
__device__ __forceinline__ float2 unpack2(unsigned long long v)
{
    float2 r;
    asm("mov.b64 {%0, %1}, %2;" : "=f"(r.x), "=f"(r.y) : "l"(v));
    return r;
}

// ---------------------------------------------------------------------------
// Weight pair-packing: w[kk][d][f] -> wp[kk][d/2][f] (b64 of two d-adjacent
// values). Reads and writes both coalesced along f.
// ---------------------------------------------------------------------------
__global__ void __launch_bounds__(256) pack_w_kernel(
    const float* __restrict__ w1, const float* __restrict__ w2)
{
    const int b = blockIdx.x;           // 0..767: tensor*384 + kk*128 + d2
    const int tensor = b / 384;
    const int kk = (b % 384) / 128;
    const int d2 = b % 128;
    const int f  = threadIdx.x;
    const float* src = (tensor == 0) ? w1 : w2;
    unsigned long long* dst = (tensor == 0) ? g_wp1 : g_wp2;
    const float a = src[kk * (DD * 256) + (2 * d2)     * 256 + f];
    const float c = src[kk * (DD * 256) + (2 * d2 + 1) * 256 + f];
    dst[kk * ((DD / 2) * 256) + d2 * 256 + f] = pack2(a, c);
}

// ---------------------------------------------------------------------------
// Fused conv1d(K=3, same pad) + bias + LayerNorm(F) + ReLU
// STAGE 0: src = x, wp = g_wp1, writes h to g_h1.
// STAGE 1: src = g_h1, wp = g_wp2, fuses the final linear + duration:
//          dur[n,l] = int(relu(h.lin_w + lin_b) + 0.5) — h2 never hits gmem.
// One block = 32 consecutive L positions, 256 threads (one per output chan f).
// Grid = 256 blocks -> 2 blocks/SM, fully resident in one wave.
// xs is reused as the LN/product tile after the mainloop (keeps static smem
// at 35 KB so 2 blocks/SM fit).
// ---------------------------------------------------------------------------
template<int STAGE>
__global__ void __launch_bounds__(256, 2) conv_ln_relu_kernel(
    const float* __restrict__ x,
    const float* __restrict__ bias,
    const float* __restrict__ gamma,
    const float* __restrict__ beta,
    const float* __restrict__ lin_w,
    const float* __restrict__ lin_b)
{
    __shared__ float xs[TP + 2][DD];   // 34.8 KB; reused as LN tile afterwards
    __shared__ float mu_s[TP];
    __shared__ float rs_s[TP];

    const float* __restrict__ src = (STAGE == 0) ? x : (const float*)g_h1;
    const unsigned long long* __restrict__ wp =
        (STAGE == 0) ? (const unsigned long long*)g_wp1
                     : (const unsigned long long*)g_wp2;

    const int blk = blockIdx.x;
    const int n   = blk / (LL / TP);
    const int l0  = (blk % (LL / TP)) * TP;
    const int f   = threadIdx.x;

    // Load input rows (zero padding at sequence edges)
    #pragma unroll
    for (int r = 0; r < TP + 2; r++) {
        int l = l0 - 1 + r;
        xs[r][f] = (l >= 0 && l < LL) ? src[(n * LL + l) * DD + f] : 0.f;
    }
    __syncthreads();

    // acc2[p] = (sum over even d, sum over odd d) packed fp32x2  (64 regs)
    unsigned long long acc2[TP];
    #pragma unroll
    for (int p = 0; p < TP; p++) acc2[p] = 0ull;

    const unsigned long long* wf = wp + f;   // this thread's column

    // Mainloop: d in steps of 4 (= 2 packed pairs).
    // Per step: 6 coalesced LDG.64 (weights), 34 LDS.128 (broadcast), 192 FFMA2.
    #pragma unroll 2
    for (int d2 = 0; d2 < DD / 2; d2 += 2) {
        unsigned long long wk01[3], wk23[3];
        #pragma unroll
        for (int kk = 0; kk < 3; kk++) {
            const unsigned long long* wkk = wf + kk * ((DD / 2) * 256);
            wk01[kk] = wkk[d2 * 256];
            wk23[kk] = wkk[(d2 + 1) * 256];
        }
        #pragma unroll
        for (int r = 0; r < TP + 2; r++) {
            // one LDS.128 -> two aligned b64 operands (broadcast across lanes)
            const ulonglong2 xv = *(const ulonglong2*)&xs[r][d2 * 2];
            #pragma unroll
            for (int kk = 0; kk < 3; kk++) {
                const int p = r - kk;      // output position using row r at tap kk
                if (p >= 0 && p < TP) {    // compile-time after unroll
                    fma2(acc2[p], xv.x, wk01[kk]);
                    fma2(acc2[p], xv.y, wk23[kk]);
                }
            }
        }
    }
    __syncthreads();   // all xs reads done; reuse xs as the h tile

    float (*hs)[DD] = xs;   // alias first TP rows

    // Horizontal combine + bias; stage into hs for LayerNorm stats
    float acc[TP];
    {
        const float bf = bias[f];
        #pragma unroll
        for (int p = 0; p < TP; p++) {
            float2 v = unpack2(acc2[p]);
            acc[p] = v.x + v.y + bf;
            hs[p][f] = acc[p];
        }
    }
    __syncthreads();

    // LayerNorm over f (256) per position p: warp-parallel reductions
    {
        const int wid = f >> 5, lane = f & 31;
        #pragma unroll
        for (int rr = 0; rr < 4; rr++) {
            int r = wid * 4 + rr;
            float s = 0.f, s2 = 0.f;
            #pragma unroll
            for (int c0 = 0; c0 < 256; c0 += 32) {
                float v = hs[r][c0 + lane];
                s += v; s2 += v * v;
            }
            #pragma unroll
            for (int o = 16; o; o >>= 1) {
                s  += __shfl_xor_sync(0xFFFFFFFFu, s,  o);
                s2 += __shfl_xor_sync(0xFFFFFFFFu, s2, o);
            }
            if (lane == 0) {
                float mu = s * (1.f / 256.f);
                float var = s2 * (1.f / 256.f) - mu * mu;
                mu_s[r] = mu;
                rs_s[r] = rsqrtf(var + 1e-5f);
            }
        }
    }
    __syncthreads();

    if (STAGE == 0) {
        const float gg = gamma[f], bb = beta[f];
        #pragma unroll
        for (int p = 0; p < TP; p++) {
            float v = (acc[p] - mu_s[p]) * rs_s[p] * gg + bb;
            g_h1[(n * LL + l0 + p) * 256 + f] = fmaxf(v, 0.f);
        }
    } else {
        // Fused linear head: prod[p][f] = relu(LN(h)) * lin_w[f], reduce over f.
        const float gg = gamma[f], bb = beta[f];
        const float lw = lin_w[f];
        #pragma unroll
        for (int p = 0; p < TP; p++) {
            float v = fmaxf((acc[p] - mu_s[p]) * rs_s[p] * gg + bb, 0.f);
            hs[p][f] = v * lw;
        }
        __syncthreads();
        {
            const int wid = f >> 5, lane = f & 31;
            const float lb = lin_b[0];
            #pragma unroll
            for (int rr = 0; rr < 4; rr++) {
                int r = wid * 4 + rr;
                float s = 0.f;
                #pragma unroll
                for (int c0 = 0; c0 < 256; c0 += 32)
                    s += hs[r][c0 + lane];
                #pragma unroll
                for (int o = 16; o; o >>= 1)
                    s += __shfl_xor_sync(0xFFFFFFFFu, s, o);
                if (lane == 0) {
                    float dpo = fmaxf(s + lb, 0.f);
                    g_dur[n * LL + l0 + r] = (int)(dpo + 0.5f);
                }
            }
        }
    }
}

// ---------------------------------------------------------------------------
// Inclusive scan of durations per row + t -> l binary-search map.
// One block per n, 512 threads. Tiny (reads 2 KB/row).
// ---------------------------------------------------------------------------
__global__ void __launch_bounds__(512) scan_map_kernel()
{
    const int n = blockIdx.x;
    const int l = threadIdx.x;

    __shared__ int sc[LL];
    sc[l] = g_dur[n * LL + l];
    __syncthreads();
    for (int off = 1; off < LL; off <<= 1) {
        int v = (l >= off) ? sc[l - off] : 0;
        __syncthreads();
        sc[l] += v;
        __syncthreads();
    }

    const int total = sc[LL - 1];
    for (int t = l; t < TT; t += LL) {
        int res = -1;
        if (t < total) {
            int lo = 0, hi = LL - 1;
            while (lo < hi) {
                int mid = (lo + hi) >> 1;
                if (sc[mid] > t) hi = mid; else lo = mid + 1;
            }
            res = lo;
        }
        g_lmap[n * TT + t] = res;
    }
}

// ---------------------------------------------------------------------------
// out[n, t, :] = x[n, lmap[n,t], :]  (or zeros). float4 streaming copy.
// ---------------------------------------------------------------------------
__global__ void __launch_bounds__(256) expand_copy_kernel(
    const float* __restrict__ x,
    float* __restrict__ out)
{
    const int idx = blockIdx.x * blockDim.x + threadIdx.x;  // over NB*TT*64 float4
    const int c = idx & 63;
    const int t = (idx >> 6) & (TT - 1);
    const int n = idx >> 18;
    const int l = g_lmap[n * TT + t];
    float4 v = make_float4(0.f, 0.f, 0.f, 0.f);
    if (l >= 0) v = ((const float4*)x)[(n * LL + l) * (DD / 4) + c];
    ((float4*)out)[idx] = v;
}

// ---------------------------------------------------------------------------
// Optional second output: WVF_pos = 1..TT (if the harness concatenated it)
// ---------------------------------------------------------------------------
__global__ void tail_kernel(float* __restrict__ out, int tail)
{
    int i = blockIdx.x * blockDim.x + threadIdx.x;
    if (i < tail) out[NB * TT * DD + i] = (float)((i % TT) + 1);
}

extern "C" void kernel_launch(void* const* d_in, const int* in_sizes, int n_in,
                              void* d_out, int out_size)
{
    const float* x       = (const float*)d_in[0];
    const float* conv1_w = (const float*)d_in[1];
    const float* conv1_b = (const float*)d_in[2];
    const float* ln1_g   = (const float*)d_in[3];
    const float* ln1_b   = (const float*)d_in[4];
    const float* conv2_w = (const float*)d_in[5];
    const float* conv2_b = (const float*)d_in[6];
    const float* ln2_g   = (const float*)d_in[7];
    const float* ln2_b   = (const float*)d_in[8];
    const float* lin_w   = (const float*)d_in[9];
    const float* lin_b   = (const float*)d_in[10];

    float* out = (float*)d_out;

    // Pure kernel launches only — fully graph-capturable.
    pack_w_kernel<<<2 * 3 * (DD / 2), 256>>>(conv1_w, conv2_w);

    const int conv_grid = NB * (LL / TP);   // 256
    conv_ln_relu_kernel<0><<<conv_grid, 256>>>(x, conv1_b, ln1_g, ln1_b, lin_w, lin_b);
    conv_ln_relu_kernel<1><<<conv_grid, 256>>>(x, conv2_b, ln2_g, ln2_b, lin_w, lin_b);
    scan_map_kernel<<<NB, LL>>>();

    const int n_f4 = NB * TT * (DD / 4);    // 4,194,304
    expand_copy_kernel<<<n_f4 / 256, 256>>>(x, out);

    const int main_elems = NB * TT * DD;
    int tail = out_size - main_elems;
    if (tail > 0) {
        tail_kernel<<<(tail + 255) / 256, 256>>>(out, tail);
    }
}